// round 1
// baseline (speedup 1.0000x reference)
#include <cuda_runtime.h>

#define NB 32
#define C 192
#define C3 576
#define T 256
#define V 25
#define TV 6400
#define S 3
#define MID 64

// Scratch (device globals — no allocation allowed in kernel_launch)
__device__ float g_qkv[NB * C3 * TV];      // 472 MB: (n, d, t, v)
__device__ float g_att[NB * S * T * T];    // 25 MB:  (n, s, t, q)
__device__ float g_y[NB * C * TV];         // 157 MB: (n, ch, t, v)

// ---------------------------------------------------------------------------
// Kernel A: qkv[n,d,tv] = sum_c w_in[d,c] * x[n,c,tv] + b_in[d]
//   M=576 (d), N=6400 (tv), K=192 (c), batch n=32
// ---------------------------------------------------------------------------
__global__ __launch_bounds__(256) void k_qkv(const float* __restrict__ x,
                                             const float* __restrict__ w,
                                             const float* __restrict__ bias) {
    __shared__ float As[16][68];  // [k][m]
    __shared__ float Bs[16][68];  // [k][p]
    const int n  = blockIdx.z;
    const int m0 = blockIdx.y * 64;
    const int p0 = blockIdx.x * 64;
    const int tid = threadIdx.x;
    const int tx = tid & 15, ty = tid >> 4;
    const float* xb = x + (size_t)n * C * TV;

    float acc[4][4];
#pragma unroll
    for (int i = 0; i < 4; i++)
#pragma unroll
        for (int j = 0; j < 4; j++) acc[i][j] = 0.f;

    for (int kk = 0; kk < C; kk += 16) {
#pragma unroll
        for (int l = 0; l < 4; l++) {
            int e = tid + l * 256;
            int k = e & 15, m = e >> 4;
            As[k][m] = w[(m0 + m) * C + kk + k];
        }
#pragma unroll
        for (int l = 0; l < 4; l++) {
            int e = tid + l * 256;
            int k = e >> 6, p = e & 63;
            Bs[k][p] = xb[(size_t)(kk + k) * TV + p0 + p];
        }
        __syncthreads();
#pragma unroll
        for (int k = 0; k < 16; k++) {
            float4 av = *(const float4*)&As[k][ty * 4];
            float4 bv = *(const float4*)&Bs[k][tx * 4];
            float a[4] = {av.x, av.y, av.z, av.w};
            float b[4] = {bv.x, bv.y, bv.z, bv.w};
#pragma unroll
            for (int i = 0; i < 4; i++)
#pragma unroll
                for (int j = 0; j < 4; j++)
                    acc[i][j] = fmaf(a[i], b[j], acc[i][j]);
        }
        __syncthreads();
    }
#pragma unroll
    for (int i = 0; i < 4; i++) {
        int d = m0 + ty * 4 + i;
        float bb = bias[d];
        float4 o;
        o.x = acc[i][0] + bb; o.y = acc[i][1] + bb;
        o.z = acc[i][2] + bb; o.w = acc[i][3] + bb;
        *(float4*)&g_qkv[(size_t)(n * C3 + d) * TV + p0 + tx * 4] = o;
    }
}

// ---------------------------------------------------------------------------
// Kernel B: att[n,s,t,q] = tanh( sum_{c,v} Q[c,t,v]*K[c,q,v] / 1600 )
//   Q channel = s*64+c, K channel = 192+s*64+c. 64x64 (t,q) tiles.
// ---------------------------------------------------------------------------
__global__ __launch_bounds__(256) void k_att() {
    __shared__ float Qs[25][68];  // [v][t]
    __shared__ float Ks[25][68];  // [v][q]
    const int ns = blockIdx.z;
    const int n = ns / S, s = ns - n * S;
    const int t0 = blockIdx.y * 64;
    const int q0 = blockIdx.x * 64;
    const int tid = threadIdx.x;
    const int tx = tid & 15, ty = tid >> 4;  // ty -> t, tx -> q
    const float* qbase = g_qkv + (size_t)(n * C3 + s * MID) * TV;
    const float* kbase = g_qkv + (size_t)(n * C3 + C + s * MID) * TV;

    float acc[4][4];
#pragma unroll
    for (int i = 0; i < 4; i++)
#pragma unroll
        for (int j = 0; j < 4; j++) acc[i][j] = 0.f;

    for (int c = 0; c < MID; c++) {
        const float* qc = qbase + (size_t)c * TV;
        const float* kc = kbase + (size_t)c * TV;
        for (int e = tid; e < 1600; e += 256) {
            int tt = e / 25, v = e - tt * 25;
            Qs[v][tt] = qc[(t0 + tt) * 25 + v];
            Ks[v][tt] = kc[(q0 + tt) * 25 + v];
        }
        __syncthreads();
#pragma unroll
        for (int v = 0; v < 25; v++) {
            float4 av = *(const float4*)&Qs[v][ty * 4];
            float4 bv = *(const float4*)&Ks[v][tx * 4];
            float a[4] = {av.x, av.y, av.z, av.w};
            float b[4] = {bv.x, bv.y, bv.z, bv.w};
#pragma unroll
            for (int i = 0; i < 4; i++)
#pragma unroll
                for (int j = 0; j < 4; j++)
                    acc[i][j] = fmaf(a[i], b[j], acc[i][j]);
        }
        __syncthreads();
    }
    const float scl = 1.f / 1600.f;
#pragma unroll
    for (int i = 0; i < 4; i++) {
        int t = t0 + ty * 4 + i;
        float4 o;
        o.x = tanhf(acc[i][0] * scl);
        o.y = tanhf(acc[i][1] * scl);
        o.z = tanhf(acc[i][2] * scl);
        o.w = tanhf(acc[i][3] * scl);
        *(float4*)&g_att[((size_t)ns * T + t) * T + q0 + tx * 4] = o;
    }
}

// ---------------------------------------------------------------------------
// Kernel C: y[n, s*64+c, t, v] = sum_q att[n,s,t,q] * Vv[c,q,v]
//   GEMM: M = t (256), N = (c,v) (1600), K = q (256), batch n*s=96
// ---------------------------------------------------------------------------
__global__ __launch_bounds__(256) void k_av() {
    __shared__ float As[16][68];  // [k=q][m=t]
    __shared__ float Bs[16][68];  // [k=q][nn=(c,v)]
    const int ns = blockIdx.z;
    const int n = ns / S, s = ns - n * S;
    const int t0  = blockIdx.y * 64;
    const int nn0 = blockIdx.x * 64;
    const int tid = threadIdx.x;
    const int tx = tid & 15, ty = tid >> 4;  // ty -> t, tx -> (c,v)
    const float* attb  = g_att + (size_t)ns * T * T;
    const float* vbase = g_qkv + (size_t)(n * C3 + 2 * C + s * MID) * TV;

    float acc[4][4];
#pragma unroll
    for (int i = 0; i < 4; i++)
#pragma unroll
        for (int j = 0; j < 4; j++) acc[i][j] = 0.f;

    for (int kk = 0; kk < T; kk += 16) {
#pragma unroll
        for (int l = 0; l < 4; l++) {
            int e = tid + l * 256;
            int k = e & 15, m = e >> 4;
            As[k][m] = attb[(t0 + m) * T + kk + k];
        }
#pragma unroll
        for (int l = 0; l < 4; l++) {
            int e = tid + l * 256;
            int k = e >> 6, p = e & 63;
            int mgl = nn0 + p;
            int c = mgl / 25, v = mgl - c * 25;
            Bs[k][p] = vbase[(size_t)c * TV + (kk + k) * 25 + v];
        }
        __syncthreads();
#pragma unroll
        for (int k = 0; k < 16; k++) {
            float4 av = *(const float4*)&As[k][ty * 4];
            float4 bv = *(const float4*)&Bs[k][tx * 4];
            float a[4] = {av.x, av.y, av.z, av.w};
            float b[4] = {bv.x, bv.y, bv.z, bv.w};
#pragma unroll
            for (int i = 0; i < 4; i++)
#pragma unroll
                for (int j = 0; j < 4; j++)
                    acc[i][j] = fmaf(a[i], b[j], acc[i][j]);
        }
        __syncthreads();
    }
#pragma unroll
    for (int i = 0; i < 4; i++) {
        int t = t0 + ty * 4 + i;
#pragma unroll
        for (int j = 0; j < 4; j++) {
            int mgl = nn0 + tx * 4 + j;
            int c = mgl / 25, v = mgl - c * 25;
            g_y[(size_t)(n * C + s * MID + c) * TV + t * 25 + v] = acc[i][j];
        }
    }
}

// ---------------------------------------------------------------------------
// Kernel D: out = LeakyReLU(x + BN(w_ff @ y + b_ff), 0.1)
//   M=192 (d), N=6400 (tv), K=192 (c), batch 32
// ---------------------------------------------------------------------------
__global__ __launch_bounds__(256) void k_ff(const float* __restrict__ x,
                                            const float* __restrict__ w,
                                            const float* __restrict__ bias,
                                            const float* __restrict__ gamma,
                                            const float* __restrict__ beta,
                                            const float* __restrict__ mean,
                                            const float* __restrict__ var,
                                            float* __restrict__ out) {
    __shared__ float As[16][68];
    __shared__ float Bs[16][68];
    const int n  = blockIdx.z;
    const int m0 = blockIdx.y * 64;
    const int p0 = blockIdx.x * 64;
    const int tid = threadIdx.x;
    const int tx = tid & 15, ty = tid >> 4;
    const float* yb = g_y + (size_t)n * C * TV;

    float acc[4][4];
#pragma unroll
    for (int i = 0; i < 4; i++)
#pragma unroll
        for (int j = 0; j < 4; j++) acc[i][j] = 0.f;

    for (int kk = 0; kk < C; kk += 16) {
#pragma unroll
        for (int l = 0; l < 4; l++) {
            int e = tid + l * 256;
            int k = e & 15, m = e >> 4;
            As[k][m] = w[(m0 + m) * C + kk + k];
        }
#pragma unroll
        for (int l = 0; l < 4; l++) {
            int e = tid + l * 256;
            int k = e >> 6, p = e & 63;
            Bs[k][p] = yb[(size_t)(kk + k) * TV + p0 + p];
        }
        __syncthreads();
#pragma unroll
        for (int k = 0; k < 16; k++) {
            float4 av = *(const float4*)&As[k][ty * 4];
            float4 bv = *(const float4*)&Bs[k][tx * 4];
            float a[4] = {av.x, av.y, av.z, av.w};
            float b[4] = {bv.x, bv.y, bv.z, bv.w};
#pragma unroll
            for (int i = 0; i < 4; i++)
#pragma unroll
                for (int j = 0; j < 4; j++)
                    acc[i][j] = fmaf(a[i], b[j], acc[i][j]);
        }
        __syncthreads();
    }
#pragma unroll
    for (int i = 0; i < 4; i++) {
        int d = m0 + ty * 4 + i;
        float sc = gamma[d] * rsqrtf(var[d] + 1e-5f);
        float sh = beta[d] - mean[d] * sc;
        float bb = bias[d];
        size_t idx = (size_t)(n * C + d) * TV + p0 + tx * 4;
        float4 xv = *(const float4*)&x[idx];
        float4 o;
        float z;
        z = xv.x + (acc[i][0] + bb) * sc + sh; o.x = z >= 0.f ? z : 0.1f * z;
        z = xv.y + (acc[i][1] + bb) * sc + sh; o.y = z >= 0.f ? z : 0.1f * z;
        z = xv.z + (acc[i][2] + bb) * sc + sh; o.z = z >= 0.f ? z : 0.1f * z;
        z = xv.w + (acc[i][3] + bb) * sc + sh; o.w = z >= 0.f ? z : 0.1f * z;
        *(float4*)&out[idx] = o;
    }
}

extern "C" void kernel_launch(void* const* d_in, const int* in_sizes, int n_in,
                              void* d_out, int out_size) {
    const float* x     = (const float*)d_in[0];
    const float* w_in  = (const float*)d_in[1];
    const float* b_in  = (const float*)d_in[2];
    const float* w_ff  = (const float*)d_in[3];
    const float* b_ff  = (const float*)d_in[4];
    const float* gamma = (const float*)d_in[5];
    const float* beta  = (const float*)d_in[6];
    const float* mean  = (const float*)d_in[7];
    const float* var   = (const float*)d_in[8];
    float* out = (float*)d_out;

    k_qkv<<<dim3(100, 9, 32), 256>>>(x, w_in, b_in);       // TV/64, C3/64, N
    k_att<<<dim3(4, 4, 96), 256>>>();                      // T/64, T/64, N*S
    k_av <<<dim3(25, 4, 96), 256>>>();                     // 1600/64, T/64, N*S
    k_ff <<<dim3(100, 3, 32), 256>>>(x, w_ff, b_ff, gamma, beta, mean, var, out);
}

// round 2
// speedup vs baseline: 3.0993x; 3.0993x over previous
#include <cuda_runtime.h>
#include <cstdint>

#define NBATCH 32
#define C 192
#define C3 576
#define T 256
#define V 25
#define TV 6400
#define S 3
#define MID 64

// Scratch (device globals — no allocation allowed)
__device__ float g_xT [NBATCH * C  * TV];   // [n][c][v][t]
__device__ float g_qkv[NBATCH * C3 * TV];   // [n][d][v][t]
__device__ float g_att[NBATCH * S * T * T]; // [n*s][q][t]
__device__ float g_y  [NBATCH * C  * TV];   // [n][ch][t][v]

__device__ __forceinline__ uint32_t f2tf(float f) {
    uint32_t r; asm("cvt.rna.tf32.f32 %0, %1;" : "=r"(r) : "f"(f)); return r;
}
__device__ __forceinline__ void mma8(float* d, const uint32_t* a, const uint32_t* b) {
    asm volatile("mma.sync.aligned.m16n8k8.row.col.f32.tf32.tf32.f32 "
        "{%0,%1,%2,%3}, {%4,%5,%6,%7}, {%8,%9}, {%0,%1,%2,%3};"
        : "+f"(d[0]), "+f"(d[1]), "+f"(d[2]), "+f"(d[3])
        : "r"(a[0]), "r"(a[1]), "r"(a[2]), "r"(a[3]), "r"(b[0]), "r"(b[1]));
}
__device__ __forceinline__ void cpa16(void* s, const void* g) {
    uint32_t sa = (uint32_t)__cvta_generic_to_shared(s);
    asm volatile("cp.async.cg.shared.global [%0], [%1], 16;" :: "r"(sa), "l"(g));
}
__device__ __forceinline__ void cpcommit() { asm volatile("cp.async.commit_group;"); }
template <int N> __device__ __forceinline__ void cpwait() {
    asm volatile("cp.async.wait_group %0;" :: "n"(N));
}

// ---------------------------------------------------------------------------
// Transpose: x[n][c][t][v] -> xT[n][c][v][t]
// ---------------------------------------------------------------------------
__global__ __launch_bounds__(256) void k_tr(const float* __restrict__ x) {
    __shared__ float sm[TV];
    size_t base = (size_t)blockIdx.x * TV;
    const int tid = threadIdx.x;
#pragma unroll
    for (int j = 0; j < 25; j++) sm[tid + j * 256] = x[base + tid + j * 256];
    __syncthreads();
#pragma unroll
    for (int j = 0; j < 25; j++) {
        int o = tid + j * 256;
        int t = o & 255, v = o >> 8;
        g_xT[base + o] = sm[t * 25 + v];
    }
}

// ---------------------------------------------------------------------------
// QKV: qkv[n][d][(v,t)] = sum_c w[d][c] * xT[n][c][(v,t)] + b[d]
// A = w  [m][k] pitch 20; B = xT [k][n] pitch 136. M=576 N=6400 K=192.
// ---------------------------------------------------------------------------
__global__ __launch_bounds__(256) void k_qkv(const float* __restrict__ w,
                                             const float* __restrict__ bias) {
    __shared__ __align__(16) float As[2][64 * 20];
    __shared__ __align__(16) float Bs[2][16 * 136];
    const int bz = blockIdx.z, m0 = blockIdx.y * 64, n0 = blockIdx.x * 128;
    const int tid = threadIdx.x, lane = tid & 31, wid = tid >> 5;
    const int g = lane >> 2, tg = lane & 3;
    const int wm = (wid >> 2) * 32, wn = (wid & 3) * 32;
    const float* Bg = g_xT + (size_t)bz * C * TV + n0;
    const int am = tid >> 2, ak = (tid & 3) * 4;
    const int bk = tid >> 5, bn = (tid & 31) * 4;

    float acc[2][4][4] = {};

    auto load = [&](int buf, int kk) {
        cpa16(&As[buf][am * 20 + ak], w + (m0 + am) * C + kk + ak);
        cpa16(&Bs[buf][bk * 136 + bn], Bg + (size_t)(kk + bk) * TV + bn);
        cpa16(&Bs[buf][(bk + 8) * 136 + bn], Bg + (size_t)(kk + bk + 8) * TV + bn);
    };
    auto compute = [&](int buf) {
#pragma unroll
        for (int ks = 0; ks < 2; ks++) {
            uint32_t a[2][4], b[4][2];
#pragma unroll
            for (int mi = 0; mi < 2; mi++) {
                const float* Ap = &As[buf][(wm + mi * 16) * 20 + ks * 8];
                a[mi][0] = f2tf(Ap[g * 20 + tg]);
                a[mi][1] = f2tf(Ap[(g + 8) * 20 + tg]);
                a[mi][2] = f2tf(Ap[g * 20 + tg + 4]);
                a[mi][3] = f2tf(Ap[(g + 8) * 20 + tg + 4]);
            }
#pragma unroll
            for (int ni = 0; ni < 4; ni++) {
                const float* Bp = &Bs[buf][ks * 8 * 136 + wn + ni * 8 + g];
                b[ni][0] = f2tf(Bp[tg * 136]);
                b[ni][1] = f2tf(Bp[(tg + 4) * 136]);
            }
#pragma unroll
            for (int mi = 0; mi < 2; mi++)
#pragma unroll
                for (int ni = 0; ni < 4; ni++) mma8(acc[mi][ni], a[mi], b[ni]);
        }
    };

    load(0, 0); cpcommit();
    for (int it = 0; it < 12; ++it) {
        if (it + 1 < 12) { load((it + 1) & 1, (it + 1) * 16); cpcommit(); cpwait<1>(); }
        else cpwait<0>();
        __syncthreads();
        compute(it & 1);
        __syncthreads();
    }
#pragma unroll
    for (int mi = 0; mi < 2; mi++) {
        int r0 = m0 + wm + mi * 16 + g;
        float b0 = bias[r0], b1 = bias[r0 + 8];
#pragma unroll
        for (int ni = 0; ni < 4; ni++) {
            int col = n0 + wn + ni * 8 + 2 * tg;
            float2 v0 = make_float2(acc[mi][ni][0] + b0, acc[mi][ni][1] + b0);
            float2 v1 = make_float2(acc[mi][ni][2] + b1, acc[mi][ni][3] + b1);
            *(float2*)&g_qkv[(size_t)(bz * C3 + r0) * TV + col] = v0;
            *(float2*)&g_qkv[(size_t)(bz * C3 + r0 + 8) * TV + col] = v1;
        }
    }
}

// ---------------------------------------------------------------------------
// Scores: att[ns][q][t] = tanh( sum_k K[k][q] * Q[k][t] / 1600 ), k=(c,v) 1600
// A = K-tensor [k][m] pitch 72; B = Q-tensor [k][n] pitch 136. M=N=256.
// ---------------------------------------------------------------------------
__global__ __launch_bounds__(256) void k_att() {
    __shared__ __align__(16) float As[2][16 * 72];
    __shared__ __align__(16) float Bs[2][16 * 136];
    const int bz = blockIdx.z;
    const int nb = bz / 3, s = bz - nb * 3;
    const int m0 = blockIdx.y * 64, n0 = blockIdx.x * 128;
    const int tid = threadIdx.x, lane = tid & 31, wid = tid >> 5;
    const int g = lane >> 2, tg = lane & 3;
    const int wm = (wid >> 2) * 32, wn = (wid & 3) * 32;
    const float* Ag = g_qkv + ((size_t)nb * C3 + C + s * MID) * TV + m0;  // K
    const float* Bg = g_qkv + ((size_t)nb * C3 + s * MID) * TV + n0;      // Q
    const int akr = tid >> 4, amq = (tid & 15) * 4;
    const int bk = tid >> 5, bn = (tid & 31) * 4;

    float acc[2][4][4] = {};

    auto load = [&](int buf, int kk) {
        cpa16(&As[buf][akr * 72 + amq], Ag + (size_t)(kk + akr) * T + amq);
        cpa16(&Bs[buf][bk * 136 + bn], Bg + (size_t)(kk + bk) * T + bn);
        cpa16(&Bs[buf][(bk + 8) * 136 + bn], Bg + (size_t)(kk + bk + 8) * T + bn);
    };
    auto compute = [&](int buf) {
#pragma unroll
        for (int ks = 0; ks < 2; ks++) {
            uint32_t a[2][4], b[4][2];
#pragma unroll
            for (int mi = 0; mi < 2; mi++) {
                const float* Ap = &As[buf][ks * 8 * 72 + wm + mi * 16];
                a[mi][0] = f2tf(Ap[tg * 72 + g]);
                a[mi][1] = f2tf(Ap[tg * 72 + g + 8]);
                a[mi][2] = f2tf(Ap[(tg + 4) * 72 + g]);
                a[mi][3] = f2tf(Ap[(tg + 4) * 72 + g + 8]);
            }
#pragma unroll
            for (int ni = 0; ni < 4; ni++) {
                const float* Bp = &Bs[buf][ks * 8 * 136 + wn + ni * 8 + g];
                b[ni][0] = f2tf(Bp[tg * 136]);
                b[ni][1] = f2tf(Bp[(tg + 4) * 136]);
            }
#pragma unroll
            for (int mi = 0; mi < 2; mi++)
#pragma unroll
                for (int ni = 0; ni < 4; ni++) mma8(acc[mi][ni], a[mi], b[ni]);
        }
    };

    load(0, 0); cpcommit();
    for (int it = 0; it < 100; ++it) {
        if (it + 1 < 100) { load((it + 1) & 1, (it + 1) * 16); cpcommit(); cpwait<1>(); }
        else cpwait<0>();
        __syncthreads();
        compute(it & 1);
        __syncthreads();
    }
    const float scl = 1.f / 1600.f;
#pragma unroll
    for (int mi = 0; mi < 2; mi++) {
        int q0r = m0 + wm + mi * 16 + g;
#pragma unroll
        for (int ni = 0; ni < 4; ni++) {
            int col = n0 + wn + ni * 8 + 2 * tg;
            float2 v0 = make_float2(tanhf(acc[mi][ni][0] * scl), tanhf(acc[mi][ni][1] * scl));
            float2 v1 = make_float2(tanhf(acc[mi][ni][2] * scl), tanhf(acc[mi][ni][3] * scl));
            *(float2*)&g_att[((size_t)bz * T + q0r) * T + col] = v0;
            *(float2*)&g_att[((size_t)bz * T + q0r + 8) * T + col] = v1;
        }
    }
}

// ---------------------------------------------------------------------------
// att·V: y[n][s*64+c][t][v] = sum_q V[(c,v)][q] * att[q][t]
// A = V-tensor [m][k] pitch 20; B = att [k][n] pitch 136. M=1600 N=256 K=256.
// Epilogue stages through smem to write y in [ch][t][v] (v-contiguous).
// ---------------------------------------------------------------------------
__global__ __launch_bounds__(256) void k_av() {
    __shared__ __align__(16) float SM[8448];
    float* As0 = SM;              // 2 x 1280
    float* Bs0 = SM + 2560;       // 2 x 2176
    const int bz = blockIdx.z;
    const int nb = bz / 3, s = bz - nb * 3;
    const int m0 = blockIdx.y * 64, n0 = blockIdx.x * 128;
    const int tid = threadIdx.x, lane = tid & 31, wid = tid >> 5;
    const int g = lane >> 2, tg = lane & 3;
    const int wm = (wid >> 2) * 32, wn = (wid & 3) * 32;
    const float* Ag = g_qkv + ((size_t)nb * C3 + 2 * C + s * MID) * TV;  // V, [m][k] stride T
    const float* Bg = g_att + (size_t)bz * T * T + n0;
    const int am = tid >> 2, ak = (tid & 3) * 4;
    const int bk = tid >> 5, bn = (tid & 31) * 4;

    float acc[2][4][4] = {};

    auto load = [&](int buf, int kk) {
        cpa16(&As0[buf * 1280 + am * 20 + ak], Ag + (size_t)(m0 + am) * T + kk + ak);
        cpa16(&Bs0[buf * 2176 + bk * 136 + bn], Bg + (size_t)(kk + bk) * T + bn);
        cpa16(&Bs0[buf * 2176 + (bk + 8) * 136 + bn], Bg + (size_t)(kk + bk + 8) * T + bn);
    };
    auto compute = [&](int buf) {
#pragma unroll
        for (int ks = 0; ks < 2; ks++) {
            uint32_t a[2][4], b[4][2];
#pragma unroll
            for (int mi = 0; mi < 2; mi++) {
                const float* Ap = &As0[buf * 1280 + (wm + mi * 16) * 20 + ks * 8];
                a[mi][0] = f2tf(Ap[g * 20 + tg]);
                a[mi][1] = f2tf(Ap[(g + 8) * 20 + tg]);
                a[mi][2] = f2tf(Ap[g * 20 + tg + 4]);
                a[mi][3] = f2tf(Ap[(g + 8) * 20 + tg + 4]);
            }
#pragma unroll
            for (int ni = 0; ni < 4; ni++) {
                const float* Bp = &Bs0[buf * 2176 + ks * 8 * 136 + wn + ni * 8 + g];
                b[ni][0] = f2tf(Bp[tg * 136]);
                b[ni][1] = f2tf(Bp[(tg + 4) * 136]);
            }
#pragma unroll
            for (int mi = 0; mi < 2; mi++)
#pragma unroll
                for (int ni = 0; ni < 4; ni++) mma8(acc[mi][ni], a[mi], b[ni]);
        }
    };

    load(0, 0); cpcommit();
    for (int it = 0; it < 16; ++it) {
        if (it + 1 < 16) { load((it + 1) & 1, (it + 1) * 16); cpcommit(); cpwait<1>(); }
        else cpwait<0>();
        __syncthreads();
        compute(it & 1);
        __syncthreads();
    }
    // stage 64x128 tile in smem (pitch 129), then write y coalesced along v
    float* Ys = SM;
#pragma unroll
    for (int mi = 0; mi < 2; mi++) {
        int r0 = wm + mi * 16 + g;
#pragma unroll
        for (int ni = 0; ni < 4; ni++) {
            int col = wn + ni * 8 + 2 * tg;
            Ys[r0 * 129 + col]       = acc[mi][ni][0];
            Ys[r0 * 129 + col + 1]   = acc[mi][ni][1];
            Ys[(r0 + 8) * 129 + col]     = acc[mi][ni][2];
            Ys[(r0 + 8) * 129 + col + 1] = acc[mi][ni][3];
        }
    }
    __syncthreads();
    const int chbase = nb * C + s * MID;
#pragma unroll
    for (int it = 0; it < 32; ++it) {
        int e = tid + it * 256;
        int m = e & 63, tcol = e >> 6;
        int mg = m0 + m;
        int c = mg / 25, v = mg - c * 25;
        g_y[((size_t)(chbase + c) * T + n0 + tcol) * V + v] = Ys[m * 129 + tcol];
    }
}

// ---------------------------------------------------------------------------
// FF + BN + residual + LeakyReLU. A = w_ff [m][k]; B = y [k][tv]. M=192.
// ---------------------------------------------------------------------------
__global__ __launch_bounds__(256) void k_ff(const float* __restrict__ x,
                                            const float* __restrict__ w,
                                            const float* __restrict__ bias,
                                            const float* __restrict__ gamma,
                                            const float* __restrict__ beta,
                                            const float* __restrict__ mean,
                                            const float* __restrict__ var,
                                            float* __restrict__ out) {
    __shared__ __align__(16) float As[2][64 * 20];
    __shared__ __align__(16) float Bs[2][16 * 136];
    const int bz = blockIdx.z, m0 = blockIdx.y * 64, n0 = blockIdx.x * 128;
    const int tid = threadIdx.x, lane = tid & 31, wid = tid >> 5;
    const int g = lane >> 2, tg = lane & 3;
    const int wm = (wid >> 2) * 32, wn = (wid & 3) * 32;
    const float* Bg = g_y + (size_t)bz * C * TV + n0;
    const int am = tid >> 2, ak = (tid & 3) * 4;
    const int bk = tid >> 5, bn = (tid & 31) * 4;

    float acc[2][4][4] = {};

    auto load = [&](int buf, int kk) {
        cpa16(&As[buf][am * 20 + ak], w + (m0 + am) * C + kk + ak);
        cpa16(&Bs[buf][bk * 136 + bn], Bg + (size_t)(kk + bk) * TV + bn);
        cpa16(&Bs[buf][(bk + 8) * 136 + bn], Bg + (size_t)(kk + bk + 8) * TV + bn);
    };
    auto compute = [&](int buf) {
#pragma unroll
        for (int ks = 0; ks < 2; ks++) {
            uint32_t a[2][4], b[4][2];
#pragma unroll
            for (int mi = 0; mi < 2; mi++) {
                const float* Ap = &As[buf][(wm + mi * 16) * 20 + ks * 8];
                a[mi][0] = f2tf(Ap[g * 20 + tg]);
                a[mi][1] = f2tf(Ap[(g + 8) * 20 + tg]);
                a[mi][2] = f2tf(Ap[g * 20 + tg + 4]);
                a[mi][3] = f2tf(Ap[(g + 8) * 20 + tg + 4]);
            }
#pragma unroll
            for (int ni = 0; ni < 4; ni++) {
                const float* Bp = &Bs[buf][ks * 8 * 136 + wn + ni * 8 + g];
                b[ni][0] = f2tf(Bp[tg * 136]);
                b[ni][1] = f2tf(Bp[(tg + 4) * 136]);
            }
#pragma unroll
            for (int mi = 0; mi < 2; mi++)
#pragma unroll
                for (int ni = 0; ni < 4; ni++) mma8(acc[mi][ni], a[mi], b[ni]);
        }
    };

    load(0, 0); cpcommit();
    for (int it = 0; it < 12; ++it) {
        if (it + 1 < 12) { load((it + 1) & 1, (it + 1) * 16); cpcommit(); cpwait<1>(); }
        else cpwait<0>();
        __syncthreads();
        compute(it & 1);
        __syncthreads();
    }
#pragma unroll
    for (int mi = 0; mi < 2; mi++) {
        int r0 = m0 + wm + mi * 16 + g;
        int r1 = r0 + 8;
        float sc0 = gamma[r0] * rsqrtf(var[r0] + 1e-5f);
        float sh0 = beta[r0] - mean[r0] * sc0;
        float bb0 = bias[r0];
        float sc1 = gamma[r1] * rsqrtf(var[r1] + 1e-5f);
        float sh1 = beta[r1] - mean[r1] * sc1;
        float bb1 = bias[r1];
#pragma unroll
        for (int ni = 0; ni < 4; ni++) {
            int col = n0 + wn + ni * 8 + 2 * tg;
            size_t i0 = (size_t)(bz * C + r0) * TV + col;
            size_t i1 = (size_t)(bz * C + r1) * TV + col;
            float2 x0 = *(const float2*)&x[i0];
            float2 x1 = *(const float2*)&x[i1];
            float z, o0x, o0y, o1x, o1y;
            z = x0.x + (acc[mi][ni][0] + bb0) * sc0 + sh0; o0x = z >= 0.f ? z : 0.1f * z;
            z = x0.y + (acc[mi][ni][1] + bb0) * sc0 + sh0; o0y = z >= 0.f ? z : 0.1f * z;
            z = x1.x + (acc[mi][ni][2] + bb1) * sc1 + sh1; o1x = z >= 0.f ? z : 0.1f * z;
            z = x1.y + (acc[mi][ni][3] + bb1) * sc1 + sh1; o1y = z >= 0.f ? z : 0.1f * z;
            *(float2*)&out[i0] = make_float2(o0x, o0y);
            *(float2*)&out[i1] = make_float2(o1x, o1y);
        }
    }
}

extern "C" void kernel_launch(void* const* d_in, const int* in_sizes, int n_in,
                              void* d_out, int out_size) {
    const float* x     = (const float*)d_in[0];
    const float* w_in  = (const float*)d_in[1];
    const float* b_in  = (const float*)d_in[2];
    const float* w_ff  = (const float*)d_in[3];
    const float* b_ff  = (const float*)d_in[4];
    const float* gamma = (const float*)d_in[5];
    const float* beta  = (const float*)d_in[6];
    const float* mean  = (const float*)d_in[7];
    const float* var   = (const float*)d_in[8];
    float* out = (float*)d_out;

    k_tr <<<NBATCH * C, 256>>>(x);
    k_qkv<<<dim3(50, 9, 32), 256>>>(w_in, b_in);
    k_att<<<dim3(2, 4, 96), 256>>>();
    k_av <<<dim3(2, 25, 96), 256>>>();
    k_ff <<<dim3(50, 3, 32), 256>>>(x, w_ff, b_ff, gamma, beta, mean, var, out);
}

// round 3
// speedup vs baseline: 3.4496x; 1.1130x over previous
#include <cuda_runtime.h>
#include <cstdint>

#define NBATCH 32
#define C 192
#define C3 576
#define T 256
#define V 25
#define TV 6400
#define S 3
#define MID 64

// Scratch (device globals — no allocation allowed). All tensor-core operands
// are stored pre-rounded to tf32 (same rounding point as round 2 -> identical numerics).
__device__ float g_xT [NBATCH * C  * TV];   // [n][c][v][t] (tf32)
__device__ float g_qkv[NBATCH * C3 * TV];   // [n][d][v][t] (tf32)
__device__ float g_att[NBATCH * S * T * T]; // [n*s][q][t]  (tf32)
__device__ float g_y  [NBATCH * C  * TV];   // [n][ch][t][v] (tf32)
__device__ float g_win[C3 * C];             // tf32 weights
__device__ float g_wff[C * C];

__device__ __forceinline__ uint32_t f2tf(float f) {
    uint32_t r; asm("cvt.rna.tf32.f32 %0, %1;" : "=r"(r) : "f"(f)); return r;
}
__device__ __forceinline__ float rnd(float f) { return __uint_as_float(f2tf(f)); }
__device__ __forceinline__ void mma8(float* d, const uint32_t* a, const uint32_t* b) {
    asm volatile("mma.sync.aligned.m16n8k8.row.col.f32.tf32.tf32.f32 "
        "{%0,%1,%2,%3}, {%4,%5,%6,%7}, {%8,%9}, {%0,%1,%2,%3};"
        : "+f"(d[0]), "+f"(d[1]), "+f"(d[2]), "+f"(d[3])
        : "r"(a[0]), "r"(a[1]), "r"(a[2]), "r"(a[3]), "r"(b[0]), "r"(b[1]));
}
__device__ __forceinline__ void cpa16(void* s, const void* g) {
    uint32_t sa = (uint32_t)__cvta_generic_to_shared(s);
    asm volatile("cp.async.cg.shared.global [%0], [%1], 16;" :: "r"(sa), "l"(g));
}
__device__ __forceinline__ void cpcommit() { asm volatile("cp.async.commit_group;"); }
template <int N> __device__ __forceinline__ void cpwait() {
    asm volatile("cp.async.wait_group %0;" :: "n"(N));
}
__device__ __forceinline__ uint32_t LDU(const float* p) { return __float_as_uint(*p); }

// ---------------------------------------------------------------------------
// Prep: round weights to tf32
// ---------------------------------------------------------------------------
__global__ __launch_bounds__(256) void k_prep(const float* __restrict__ w_in,
                                              const float* __restrict__ w_ff) {
    int i = blockIdx.x * 256 + threadIdx.x;
    if (i < C3 * C) g_win[i] = rnd(w_in[i]);
    if (i < C * C)  g_wff[i] = rnd(w_ff[i]);
}

// ---------------------------------------------------------------------------
// Transpose + round: x[n][c][t][v] -> xT[n][c][v][t] (tf32)
// ---------------------------------------------------------------------------
__global__ __launch_bounds__(256) void k_tr(const float* __restrict__ x) {
    __shared__ float sm[TV];
    size_t base = (size_t)blockIdx.x * TV;
    const int tid = threadIdx.x;
#pragma unroll
    for (int j = 0; j < 25; j++) sm[tid + j * 256] = x[base + tid + j * 256];
    __syncthreads();
#pragma unroll
    for (int j = 0; j < 25; j++) {
        int o = tid + j * 256;
        int t = o & 255, v = o >> 8;
        g_xT[base + o] = rnd(sm[t * 25 + v]);
    }
}

// ---------------------------------------------------------------------------
// QKV: qkv[n][d][(v,t)] = sum_c w[d][c] * xT[n][c][(v,t)] + b[d]
// Block 64x256, warp 32x64 (8 warps 2x4). M=576 N=6400 K=192.
// ---------------------------------------------------------------------------
__global__ __launch_bounds__(256) void k_qkv(const float* __restrict__ bias) {
    __shared__ __align__(16) float As[2][64 * 20];
    __shared__ __align__(16) float Bs[2][16 * 264];
    const int bz = blockIdx.z, m0 = blockIdx.y * 64, n0 = blockIdx.x * 256;
    const int tid = threadIdx.x, lane = tid & 31, wid = tid >> 5;
    const int g = lane >> 2, tg = lane & 3;
    const int wm = (wid >> 2) * 32, wn = (wid & 3) * 64;
    const float* Bg = g_xT + (size_t)bz * C * TV + n0;
    const float* Wg = g_win;
    const int am = tid >> 2, ak = (tid & 3) * 4;
    const int bk = tid >> 6, bn = (tid & 63) * 4;

    float acc[2][8][4] = {};

    auto load = [&](int buf, int kk) {
        cpa16(&As[buf][am * 20 + ak], Wg + (m0 + am) * C + kk + ak);
#pragma unroll
        for (int r = 0; r < 16; r += 4)
            cpa16(&Bs[buf][(bk + r) * 264 + bn], Bg + (size_t)(kk + bk + r) * TV + bn);
    };
    auto compute = [&](int buf) {
#pragma unroll
        for (int ks = 0; ks < 2; ks++) {
            uint32_t a[2][4], b[8][2];
#pragma unroll
            for (int mi = 0; mi < 2; mi++) {
                const float* Ap = &As[buf][(wm + mi * 16) * 20 + ks * 8];
                a[mi][0] = LDU(Ap + g * 20 + tg);
                a[mi][1] = LDU(Ap + (g + 8) * 20 + tg);
                a[mi][2] = LDU(Ap + g * 20 + tg + 4);
                a[mi][3] = LDU(Ap + (g + 8) * 20 + tg + 4);
            }
#pragma unroll
            for (int ni = 0; ni < 8; ni++) {
                const float* Bp = &Bs[buf][ks * 8 * 264 + wn + ni * 8 + g];
                b[ni][0] = LDU(Bp + tg * 264);
                b[ni][1] = LDU(Bp + (tg + 4) * 264);
            }
#pragma unroll
            for (int mi = 0; mi < 2; mi++)
#pragma unroll
                for (int ni = 0; ni < 8; ni++) mma8(acc[mi][ni], a[mi], b[ni]);
        }
    };

    load(0, 0); cpcommit();
    for (int it = 0; it < 12; ++it) {
        if (it + 1 < 12) { load((it + 1) & 1, (it + 1) * 16); cpcommit(); cpwait<1>(); }
        else cpwait<0>();
        __syncthreads();
        compute(it & 1);
        __syncthreads();
    }
#pragma unroll
    for (int mi = 0; mi < 2; mi++) {
        int r0 = m0 + wm + mi * 16 + g;
        float b0 = bias[r0], b1 = bias[r0 + 8];
#pragma unroll
        for (int ni = 0; ni < 8; ni++) {
            int col = n0 + wn + ni * 8 + 2 * tg;
            float2 v0 = make_float2(rnd(acc[mi][ni][0] + b0), rnd(acc[mi][ni][1] + b0));
            float2 v1 = make_float2(rnd(acc[mi][ni][2] + b1), rnd(acc[mi][ni][3] + b1));
            *(float2*)&g_qkv[(size_t)(bz * C3 + r0) * TV + col] = v0;
            *(float2*)&g_qkv[(size_t)(bz * C3 + r0 + 8) * TV + col] = v1;
        }
    }
}

// ---------------------------------------------------------------------------
// Scores: att[ns][q][t] = tanh( sum_k K[k][q] * Q[k][t] / 1600 ), k flat 1600
// Block 128x128, warp 64x32 (8 warps 2x4). M=N=256, K=1600.
// ---------------------------------------------------------------------------
__global__ __launch_bounds__(256) void k_att() {
    __shared__ __align__(16) float As[2][16 * 136];
    __shared__ __align__(16) float Bs[2][16 * 136];
    const int bz = blockIdx.z;
    const int nb = bz / 3, s = bz - nb * 3;
    const int m0 = blockIdx.y * 128, n0 = blockIdx.x * 128;
    const int tid = threadIdx.x, lane = tid & 31, wid = tid >> 5;
    const int g = lane >> 2, tg = lane & 3;
    const int wm = (wid >> 2) * 64, wn = (wid & 3) * 32;
    const float* Ag = g_qkv + ((size_t)nb * C3 + C + s * MID) * TV + m0;  // K
    const float* Bg = g_qkv + ((size_t)nb * C3 + s * MID) * TV + n0;      // Q
    const int lr = tid >> 5, lc = (tid & 31) * 4;

    float acc[4][4][4] = {};

    auto load = [&](int buf, int kk) {
        cpa16(&As[buf][lr * 136 + lc], Ag + (size_t)(kk + lr) * T + lc);
        cpa16(&As[buf][(lr + 8) * 136 + lc], Ag + (size_t)(kk + lr + 8) * T + lc);
        cpa16(&Bs[buf][lr * 136 + lc], Bg + (size_t)(kk + lr) * T + lc);
        cpa16(&Bs[buf][(lr + 8) * 136 + lc], Bg + (size_t)(kk + lr + 8) * T + lc);
    };
    auto compute = [&](int buf) {
#pragma unroll
        for (int ks = 0; ks < 2; ks++) {
            uint32_t a[4][4], b[4][2];
#pragma unroll
            for (int mi = 0; mi < 4; mi++) {
                const float* Ap = &As[buf][ks * 8 * 136 + wm + mi * 16];
                a[mi][0] = LDU(Ap + tg * 136 + g);
                a[mi][1] = LDU(Ap + tg * 136 + g + 8);
                a[mi][2] = LDU(Ap + (tg + 4) * 136 + g);
                a[mi][3] = LDU(Ap + (tg + 4) * 136 + g + 8);
            }
#pragma unroll
            for (int ni = 0; ni < 4; ni++) {
                const float* Bp = &Bs[buf][ks * 8 * 136 + wn + ni * 8 + g];
                b[ni][0] = LDU(Bp + tg * 136);
                b[ni][1] = LDU(Bp + (tg + 4) * 136);
            }
#pragma unroll
            for (int mi = 0; mi < 4; mi++)
#pragma unroll
                for (int ni = 0; ni < 4; ni++) mma8(acc[mi][ni], a[mi], b[ni]);
        }
    };

    load(0, 0); cpcommit();
    for (int it = 0; it < 100; ++it) {
        if (it + 1 < 100) { load((it + 1) & 1, (it + 1) * 16); cpcommit(); cpwait<1>(); }
        else cpwait<0>();
        __syncthreads();
        compute(it & 1);
        __syncthreads();
    }
    const float scl = 1.f / 1600.f;
#pragma unroll
    for (int mi = 0; mi < 4; mi++) {
        int q0r = m0 + wm + mi * 16 + g;
#pragma unroll
        for (int ni = 0; ni < 4; ni++) {
            int col = n0 + wn + ni * 8 + 2 * tg;
            float2 v0 = make_float2(rnd(tanhf(acc[mi][ni][0] * scl)), rnd(tanhf(acc[mi][ni][1] * scl)));
            float2 v1 = make_float2(rnd(tanhf(acc[mi][ni][2] * scl)), rnd(tanhf(acc[mi][ni][3] * scl)));
            *(float2*)&g_att[((size_t)bz * T + q0r) * T + col] = v0;
            *(float2*)&g_att[((size_t)bz * T + q0r + 8) * T + col] = v1;
        }
    }
}

// ---------------------------------------------------------------------------
// att.V: y[n][s*64+c][t][v] = sum_q V[(c,v)][q] * att[q][t]
// Block 64x128, warp 32x32. M=1600 N=256 K=256. Epilogue transposes via smem.
// ---------------------------------------------------------------------------
__global__ __launch_bounds__(256) void k_av() {
    __shared__ __align__(16) float SM[8448];
    float* As0 = SM;              // 2 x 1280
    float* Bs0 = SM + 2560;       // 2 x 2176
    const int bz = blockIdx.z;
    const int nb = bz / 3, s = bz - nb * 3;
    const int m0 = blockIdx.y * 64, n0 = blockIdx.x * 128;
    const int tid = threadIdx.x, lane = tid & 31, wid = tid >> 5;
    const int g = lane >> 2, tg = lane & 3;
    const int wm = (wid >> 2) * 32, wn = (wid & 3) * 32;
    const float* Ag = g_qkv + ((size_t)nb * C3 + 2 * C + s * MID) * TV;  // V [m][k]
    const float* Bg = g_att + (size_t)bz * T * T + n0;
    const int am = tid >> 2, ak = (tid & 3) * 4;
    const int bk = tid >> 5, bn = (tid & 31) * 4;

    float acc[2][4][4] = {};

    auto load = [&](int buf, int kk) {
        cpa16(&As0[buf * 1280 + am * 20 + ak], Ag + (size_t)(m0 + am) * T + kk + ak);
        cpa16(&Bs0[buf * 2176 + bk * 136 + bn], Bg + (size_t)(kk + bk) * T + bn);
        cpa16(&Bs0[buf * 2176 + (bk + 8) * 136 + bn], Bg + (size_t)(kk + bk + 8) * T + bn);
    };
    auto compute = [&](int buf) {
#pragma unroll
        for (int ks = 0; ks < 2; ks++) {
            uint32_t a[2][4], b[4][2];
#pragma unroll
            for (int mi = 0; mi < 2; mi++) {
                const float* Ap = &As0[buf * 1280 + (wm + mi * 16) * 20 + ks * 8];
                a[mi][0] = LDU(Ap + g * 20 + tg);
                a[mi][1] = LDU(Ap + (g + 8) * 20 + tg);
                a[mi][2] = LDU(Ap + g * 20 + tg + 4);
                a[mi][3] = LDU(Ap + (g + 8) * 20 + tg + 4);
            }
#pragma unroll
            for (int ni = 0; ni < 4; ni++) {
                const float* Bp = &Bs0[buf * 2176 + ks * 8 * 136 + wn + ni * 8 + g];
                b[ni][0] = LDU(Bp + tg * 136);
                b[ni][1] = LDU(Bp + (tg + 4) * 136);
            }
#pragma unroll
            for (int mi = 0; mi < 2; mi++)
#pragma unroll
                for (int ni = 0; ni < 4; ni++) mma8(acc[mi][ni], a[mi], b[ni]);
        }
    };

    load(0, 0); cpcommit();
    for (int it = 0; it < 16; ++it) {
        if (it + 1 < 16) { load((it + 1) & 1, (it + 1) * 16); cpcommit(); cpwait<1>(); }
        else cpwait<0>();
        __syncthreads();
        compute(it & 1);
        __syncthreads();
    }
    // stage 64x128 tile in smem (pitch 129), then write y coalesced along v (tf32)
    float* Ys = SM;
#pragma unroll
    for (int mi = 0; mi < 2; mi++) {
        int r0 = wm + mi * 16 + g;
#pragma unroll
        for (int ni = 0; ni < 4; ni++) {
            int col = wn + ni * 8 + 2 * tg;
            Ys[r0 * 129 + col]           = acc[mi][ni][0];
            Ys[r0 * 129 + col + 1]       = acc[mi][ni][1];
            Ys[(r0 + 8) * 129 + col]     = acc[mi][ni][2];
            Ys[(r0 + 8) * 129 + col + 1] = acc[mi][ni][3];
        }
    }
    __syncthreads();
    const int chbase = nb * C + s * MID;
#pragma unroll
    for (int it = 0; it < 32; ++it) {
        int e = tid + it * 256;
        int m = e & 63, tcol = e >> 6;
        int mg = m0 + m;
        int c = mg / 25, v = mg - c * 25;
        g_y[((size_t)(chbase + c) * T + n0 + tcol) * V + v] = rnd(Ys[m * 129 + tcol]);
    }
}

// ---------------------------------------------------------------------------
// FF + BN + residual + LeakyReLU. Block 64x256, warp 32x64. M=192 N=6400 K=192.
// ---------------------------------------------------------------------------
__global__ __launch_bounds__(256) void k_ff(const float* __restrict__ x,
                                            const float* __restrict__ bias,
                                            const float* __restrict__ gamma,
                                            const float* __restrict__ beta,
                                            const float* __restrict__ mean,
                                            const float* __restrict__ var,
                                            float* __restrict__ out) {
    __shared__ __align__(16) float As[2][64 * 20];
    __shared__ __align__(16) float Bs[2][16 * 264];
    const int bz = blockIdx.z, m0 = blockIdx.y * 64, n0 = blockIdx.x * 256;
    const int tid = threadIdx.x, lane = tid & 31, wid = tid >> 5;
    const int g = lane >> 2, tg = lane & 3;
    const int wm = (wid >> 2) * 32, wn = (wid & 3) * 64;
    const float* Bg = g_y + (size_t)bz * C * TV + n0;
    const int am = tid >> 2, ak = (tid & 3) * 4;
    const int bk = tid >> 6, bn = (tid & 63) * 4;

    float acc[2][8][4] = {};

    auto load = [&](int buf, int kk) {
        cpa16(&As[buf][am * 20 + ak], g_wff + (m0 + am) * C + kk + ak);
#pragma unroll
        for (int r = 0; r < 16; r += 4)
            cpa16(&Bs[buf][(bk + r) * 264 + bn], Bg + (size_t)(kk + bk + r) * TV + bn);
    };
    auto compute = [&](int buf) {
#pragma unroll
        for (int ks = 0; ks < 2; ks++) {
            uint32_t a[2][4], b[8][2];
#pragma unroll
            for (int mi = 0; mi < 2; mi++) {
                const float* Ap = &As[buf][(wm + mi * 16) * 20 + ks * 8];
                a[mi][0] = LDU(Ap + g * 20 + tg);
                a[mi][1] = LDU(Ap + (g + 8) * 20 + tg);
                a[mi][2] = LDU(Ap + g * 20 + tg + 4);
                a[mi][3] = LDU(Ap + (g + 8) * 20 + tg + 4);
            }
#pragma unroll
            for (int ni = 0; ni < 8; ni++) {
                const float* Bp = &Bs[buf][ks * 8 * 264 + wn + ni * 8 + g];
                b[ni][0] = LDU(Bp + tg * 264);
                b[ni][1] = LDU(Bp + (tg + 4) * 264);
            }
#pragma unroll
            for (int mi = 0; mi < 2; mi++)
#pragma unroll
                for (int ni = 0; ni < 8; ni++) mma8(acc[mi][ni], a[mi], b[ni]);
        }
    };

    load(0, 0); cpcommit();
    for (int it = 0; it < 12; ++it) {
        if (it + 1 < 12) { load((it + 1) & 1, (it + 1) * 16); cpcommit(); cpwait<1>(); }
        else cpwait<0>();
        __syncthreads();
        compute(it & 1);
        __syncthreads();
    }
#pragma unroll
    for (int mi = 0; mi < 2; mi++) {
        int r0 = m0 + wm + mi * 16 + g;
        int r1 = r0 + 8;
        float sc0 = gamma[r0] * rsqrtf(var[r0] + 1e-5f);
        float sh0 = beta[r0] - mean[r0] * sc0;
        float bb0 = bias[r0];
        float sc1 = gamma[r1] * rsqrtf(var[r1] + 1e-5f);
        float sh1 = beta[r1] - mean[r1] * sc1;
        float bb1 = bias[r1];
#pragma unroll
        for (int ni = 0; ni < 8; ni++) {
            int col = n0 + wn + ni * 8 + 2 * tg;
            size_t i0 = (size_t)(bz * C + r0) * TV + col;
            size_t i1 = (size_t)(bz * C + r1) * TV + col;
            float2 x0 = *(const float2*)&x[i0];
            float2 x1 = *(const float2*)&x[i1];
            float z, o0x, o0y, o1x, o1y;
            z = x0.x + (acc[mi][ni][0] + bb0) * sc0 + sh0; o0x = z >= 0.f ? z : 0.1f * z;
            z = x0.y + (acc[mi][ni][1] + bb0) * sc0 + sh0; o0y = z >= 0.f ? z : 0.1f * z;
            z = x1.x + (acc[mi][ni][2] + bb1) * sc1 + sh1; o1x = z >= 0.f ? z : 0.1f * z;
            z = x1.y + (acc[mi][ni][3] + bb1) * sc1 + sh1; o1y = z >= 0.f ? z : 0.1f * z;
            *(float2*)&out[i0] = make_float2(o0x, o0y);
            *(float2*)&out[i1] = make_float2(o1x, o1y);
        }
    }
}

extern "C" void kernel_launch(void* const* d_in, const int* in_sizes, int n_in,
                              void* d_out, int out_size) {
    const float* x     = (const float*)d_in[0];
    const float* w_in  = (const float*)d_in[1];
    const float* b_in  = (const float*)d_in[2];
    const float* w_ff  = (const float*)d_in[3];
    const float* b_ff  = (const float*)d_in[4];
    const float* gamma = (const float*)d_in[5];
    const float* beta  = (const float*)d_in[6];
    const float* mean  = (const float*)d_in[7];
    const float* var   = (const float*)d_in[8];
    float* out = (float*)d_out;

    k_prep<<<432, 256>>>(w_in, w_ff);
    k_tr <<<NBATCH * C, 256>>>(x);
    k_qkv<<<dim3(25, 9, 32), 256>>>(b_in);
    k_att<<<dim3(2, 2, 96), 256>>>();
    k_av <<<dim3(2, 25, 96), 256>>>();
    k_ff <<<dim3(25, 3, 32), 256>>>(x, b_ff, gamma, beta, mean, var, out);
}

// round 5
// speedup vs baseline: 3.4934x; 1.0127x over previous
#include <cuda_runtime.h>
#include <cstdint>

#define NBATCH 32
#define C 192
#define C3 576
#define T 256
#define V 25
#define TV 6400
#define S 3
#define MID 64

// Scratch (device globals). All tensor-core operands stored pre-rounded to tf32.
__device__ float g_xT [NBATCH * C  * TV];   // [n][c][v][t] (tf32)
__device__ float g_qkv[NBATCH * C3 * TV];   // [n][d][v][t] (tf32)
__device__ float g_att[NBATCH * S * T * T]; // [n*s][q][t]  (tf32)
__device__ float g_y  [NBATCH * C  * TV];   // [n][ch][t][v] (tf32)
__device__ float g_win[C3 * C];             // tf32 weights
__device__ float g_wff[C * C];

__device__ __forceinline__ uint32_t f2tf(float f) {
    uint32_t r; asm("cvt.rna.tf32.f32 %0, %1;" : "=r"(r) : "f"(f)); return r;
}
__device__ __forceinline__ float rnd(float f) { return __uint_as_float(f2tf(f)); }
__device__ __forceinline__ void mma8(float* d, const uint32_t* a, const uint32_t* b) {
    asm volatile("mma.sync.aligned.m16n8k8.row.col.f32.tf32.tf32.f32 "
        "{%0,%1,%2,%3}, {%4,%5,%6,%7}, {%8,%9}, {%0,%1,%2,%3};"
        : "+f"(d[0]), "+f"(d[1]), "+f"(d[2]), "+f"(d[3])
        : "r"(a[0]), "r"(a[1]), "r"(a[2]), "r"(a[3]), "r"(b[0]), "r"(b[1]));
}
__device__ __forceinline__ void cpa16(void* s, const void* g) {
    uint32_t sa = (uint32_t)__cvta_generic_to_shared(s);
    asm volatile("cp.async.cg.shared.global [%0], [%1], 16;" :: "r"(sa), "l"(g));
}
__device__ __forceinline__ void cpcommit() { asm volatile("cp.async.commit_group;"); }
template <int N> __device__ __forceinline__ void cpwait() {
    asm volatile("cp.async.wait_group %0;" :: "n"(N));
}
__device__ __forceinline__ uint32_t LDU(const float* p) { return __float_as_uint(*p); }

// ---------------------------------------------------------------------------
__global__ __launch_bounds__(256) void k_prep(const float* __restrict__ w_in,
                                              const float* __restrict__ w_ff) {
    int i = blockIdx.x * 256 + threadIdx.x;
    if (i < C3 * C) g_win[i] = rnd(w_in[i]);
    if (i < C * C)  g_wff[i] = rnd(w_ff[i]);
}

// x[n][c][t][v] -> xT[n][c][v][t] (tf32)
__global__ __launch_bounds__(256) void k_tr(const float* __restrict__ x) {
    __shared__ float sm[TV];
    size_t base = (size_t)blockIdx.x * TV;
    const int tid = threadIdx.x;
#pragma unroll
    for (int j = 0; j < 25; j++) sm[tid + j * 256] = x[base + tid + j * 256];
    __syncthreads();
#pragma unroll
    for (int j = 0; j < 25; j++) {
        int o = tid + j * 256;
        int t = o & 255, v = o >> 8;
        g_xT[base + o] = rnd(sm[t * 25 + v]);
    }
}

// ---------------------------------------------------------------------------
// QKV: block 64x256, warp 32x64, 3-stage pipeline, 1 sync/iter. K=192.
// ---------------------------------------------------------------------------
__global__ __launch_bounds__(256) void k_qkv(const float* __restrict__ bias) {
    __shared__ __align__(16) float As[3][64 * 20];
    __shared__ __align__(16) float Bs[3][16 * 264];
    const int bz = blockIdx.z, m0 = blockIdx.y * 64, n0 = blockIdx.x * 256;
    const int tid = threadIdx.x, lane = tid & 31, wid = tid >> 5;
    const int g = lane >> 2, tg = lane & 3;
    const int wm = (wid >> 2) * 32, wn = (wid & 3) * 64;
    const float* Bg = g_xT + (size_t)bz * C * TV + n0;
    const int am = tid >> 2, ak = (tid & 3) * 4;
    const int bk = tid >> 6, bn = (tid & 63) * 4;

    float acc[2][8][4] = {};

    auto load = [&](int buf, int kk) {
        cpa16(&As[buf][am * 20 + ak], g_win + (m0 + am) * C + kk + ak);
#pragma unroll
        for (int r = 0; r < 16; r += 4)
            cpa16(&Bs[buf][(bk + r) * 264 + bn], Bg + (size_t)(kk + bk + r) * TV + bn);
    };
    auto compute = [&](int buf) {
#pragma unroll
        for (int ks = 0; ks < 2; ks++) {
            uint32_t a[2][4], b[8][2];
#pragma unroll
            for (int mi = 0; mi < 2; mi++) {
                const float* Ap = &As[buf][(wm + mi * 16) * 20 + ks * 8];
                a[mi][0] = LDU(Ap + g * 20 + tg);
                a[mi][1] = LDU(Ap + (g + 8) * 20 + tg);
                a[mi][2] = LDU(Ap + g * 20 + tg + 4);
                a[mi][3] = LDU(Ap + (g + 8) * 20 + tg + 4);
            }
#pragma unroll
            for (int ni = 0; ni < 8; ni++) {
                const float* Bp = &Bs[buf][ks * 8 * 264 + wn + ni * 8 + g];
                b[ni][0] = LDU(Bp + tg * 264);
                b[ni][1] = LDU(Bp + (tg + 4) * 264);
            }
#pragma unroll
            for (int mi = 0; mi < 2; mi++)
#pragma unroll
                for (int ni = 0; ni < 8; ni++) mma8(acc[mi][ni], a[mi], b[ni]);
        }
    };

    load(0, 0); cpcommit();
    load(1, 16); cpcommit();
    const int NIT = 12;
    for (int it = 0; it < NIT; ++it) {
        cpwait<1>();
        __syncthreads();
        int nx = it + 2;
        if (nx < NIT) load(nx - nx / 3 * 3, nx * 16);
        compute(it - it / 3 * 3);
        cpcommit();
    }
#pragma unroll
    for (int mi = 0; mi < 2; mi++) {
        int r0 = m0 + wm + mi * 16 + g;
        float b0 = bias[r0], b1 = bias[r0 + 8];
#pragma unroll
        for (int ni = 0; ni < 8; ni++) {
            int col = n0 + wn + ni * 8 + 2 * tg;
            float2 v0 = make_float2(rnd(acc[mi][ni][0] + b0), rnd(acc[mi][ni][1] + b0));
            float2 v1 = make_float2(rnd(acc[mi][ni][2] + b1), rnd(acc[mi][ni][3] + b1));
            *(float2*)&g_qkv[(size_t)(bz * C3 + r0) * TV + col] = v0;
            *(float2*)&g_qkv[(size_t)(bz * C3 + r0 + 8) * TV + col] = v1;
        }
    }
}

// ---------------------------------------------------------------------------
// Scores: att[ns][q][t] = tanh(sum_k K[k][q]*Q[k][t]/1600), K=1600.
// Block 64x128, warp 32x32, 3-stage, 1 sync/iter. Grid 768 blocks.
// ---------------------------------------------------------------------------
__global__ __launch_bounds__(256) void k_att() {
    __shared__ __align__(16) float As[3][16 * 72];
    __shared__ __align__(16) float Bs[3][16 * 136];
    const int bz = blockIdx.z;
    const int nb = bz / 3, s = bz - nb * 3;
    const int m0 = blockIdx.y * 64, n0 = blockIdx.x * 128;
    const int tid = threadIdx.x, lane = tid & 31, wid = tid >> 5;
    const int g = lane >> 2, tg = lane & 3;
    const int wm = (wid >> 2) * 32, wn = (wid & 3) * 32;
    const float* Ag = g_qkv + ((size_t)nb * C3 + C + s * MID) * TV + m0;  // K [k][m]
    const float* Bg = g_qkv + ((size_t)nb * C3 + s * MID) * TV + n0;      // Q [k][n]
    const int ar = tid >> 4, ac = (tid & 15) * 4;
    const int br = tid >> 5, bc = (tid & 31) * 4;

    float acc[2][4][4] = {};

    auto load = [&](int buf, int kk) {
        cpa16(&As[buf][ar * 72 + ac], Ag + (size_t)(kk + ar) * T + ac);
        cpa16(&Bs[buf][br * 136 + bc], Bg + (size_t)(kk + br) * T + bc);
        cpa16(&Bs[buf][(br + 8) * 136 + bc], Bg + (size_t)(kk + br + 8) * T + bc);
    };
    auto compute = [&](int buf) {
#pragma unroll
        for (int ks = 0; ks < 2; ks++) {
            uint32_t a[2][4], b[4][2];
#pragma unroll
            for (int mi = 0; mi < 2; mi++) {
                const float* Ap = &As[buf][ks * 8 * 72 + wm + mi * 16];
                a[mi][0] = LDU(Ap + tg * 72 + g);
                a[mi][1] = LDU(Ap + tg * 72 + g + 8);
                a[mi][2] = LDU(Ap + (tg + 4) * 72 + g);
                a[mi][3] = LDU(Ap + (tg + 4) * 72 + g + 8);
            }
#pragma unroll
            for (int ni = 0; ni < 4; ni++) {
                const float* Bp = &Bs[buf][ks * 8 * 136 + wn + ni * 8 + g];
                b[ni][0] = LDU(Bp + tg * 136);
                b[ni][1] = LDU(Bp + (tg + 4) * 136);
            }
#pragma unroll
            for (int mi = 0; mi < 2; mi++)
#pragma unroll
                for (int ni = 0; ni < 4; ni++) mma8(acc[mi][ni], a[mi], b[ni]);
        }
    };

    load(0, 0); cpcommit();
    load(1, 16); cpcommit();
    const int NIT = 100;
    for (int it = 0; it < NIT; ++it) {
        cpwait<1>();
        __syncthreads();
        int nx = it + 2;
        if (nx < NIT) load(nx - nx / 3 * 3, nx * 16);
        compute(it - it / 3 * 3);
        cpcommit();
    }
    const float scl = 1.f / 1600.f;
#pragma unroll
    for (int mi = 0; mi < 2; mi++) {
        int q0r = m0 + wm + mi * 16 + g;
#pragma unroll
        for (int ni = 0; ni < 4; ni++) {
            int col = n0 + wn + ni * 8 + 2 * tg;
            float2 v0 = make_float2(rnd(tanhf(acc[mi][ni][0] * scl)), rnd(tanhf(acc[mi][ni][1] * scl)));
            float2 v1 = make_float2(rnd(tanhf(acc[mi][ni][2] * scl)), rnd(tanhf(acc[mi][ni][3] * scl)));
            *(float2*)&g_att[((size_t)bz * T + q0r) * T + col] = v0;
            *(float2*)&g_att[((size_t)bz * T + q0r + 8) * T + col] = v1;
        }
    }
}

// ---------------------------------------------------------------------------
// att.V: block 64x128, warp 32x32, 3-stage, 1 sync/iter. K=256.
// ---------------------------------------------------------------------------
__global__ __launch_bounds__(256) void k_av() {
    __shared__ __align__(16) float SM[3 * 1280 + 3 * 2176];  // 10368 floats
    float* As0 = SM;              // 3 x 1280
    float* Bs0 = SM + 3 * 1280;   // 3 x 2176
    const int bz = blockIdx.z;
    const int nb = bz / 3, s = bz - nb * 3;
    const int m0 = blockIdx.y * 64, n0 = blockIdx.x * 128;
    const int tid = threadIdx.x, lane = tid & 31, wid = tid >> 5;
    const int g = lane >> 2, tg = lane & 3;
    const int wm = (wid >> 2) * 32, wn = (wid & 3) * 32;
    const float* Ag = g_qkv + ((size_t)nb * C3 + 2 * C + s * MID) * TV;  // V [m][k]
    const float* Bg = g_att + (size_t)bz * T * T + n0;
    const int am = tid >> 2, ak = (tid & 3) * 4;
    const int bk = tid >> 5, bn = (tid & 31) * 4;

    float acc[2][4][4] = {};

    auto load = [&](int buf, int kk) {
        cpa16(&As0[buf * 1280 + am * 20 + ak], Ag + (size_t)(m0 + am) * T + kk + ak);
        cpa16(&Bs0[buf * 2176 + bk * 136 + bn], Bg + (size_t)(kk + bk) * T + bn);
        cpa16(&Bs0[buf * 2176 + (bk + 8) * 136 + bn], Bg + (size_t)(kk + bk + 8) * T + bn);
    };
    auto compute = [&](int buf) {
#pragma unroll
        for (int ks = 0; ks < 2; ks++) {
            uint32_t a[2][4], b[4][2];
#pragma unroll
            for (int mi = 0; mi < 2; mi++) {
                const float* Ap = &As0[buf * 1280 + (wm + mi * 16) * 20 + ks * 8];
                a[mi][0] = LDU(Ap + g * 20 + tg);
                a[mi][1] = LDU(Ap + (g + 8) * 20 + tg);
                a[mi][2] = LDU(Ap + g * 20 + tg + 4);
                a[mi][3] = LDU(Ap + (g + 8) * 20 + tg + 4);
            }
#pragma unroll
            for (int ni = 0; ni < 4; ni++) {
                const float* Bp = &Bs0[buf * 2176 + ks * 8 * 136 + wn + ni * 8 + g];
                b[ni][0] = LDU(Bp + tg * 136);
                b[ni][1] = LDU(Bp + (tg + 4) * 136);
            }
#pragma unroll
            for (int mi = 0; mi < 2; mi++)
#pragma unroll
                for (int ni = 0; ni < 4; ni++) mma8(acc[mi][ni], a[mi], b[ni]);
        }
    };

    load(0, 0); cpcommit();
    load(1, 16); cpcommit();
    const int NIT = 16;
    for (int it = 0; it < NIT; ++it) {
        cpwait<1>();
        __syncthreads();
        int nx = it + 2;
        if (nx < NIT) load(nx - nx / 3 * 3, nx * 16);
        compute(it - it / 3 * 3);
        cpcommit();
    }
    __syncthreads();
    // stage 64x128 tile in smem (pitch 129), then write y coalesced along v (tf32)
    float* Ys = SM;
#pragma unroll
    for (int mi = 0; mi < 2; mi++) {
        int r0 = wm + mi * 16 + g;
#pragma unroll
        for (int ni = 0; ni < 4; ni++) {
            int col = wn + ni * 8 + 2 * tg;
            Ys[r0 * 129 + col]           = acc[mi][ni][0];
            Ys[r0 * 129 + col + 1]       = acc[mi][ni][1];
            Ys[(r0 + 8) * 129 + col]     = acc[mi][ni][2];
            Ys[(r0 + 8) * 129 + col + 1] = acc[mi][ni][3];
        }
    }
    __syncthreads();
    const int chbase = nb * C + s * MID;
#pragma unroll
    for (int it = 0; it < 32; ++it) {
        int e = tid + it * 256;
        int m = e & 63, tcol = e >> 6;
        int mg = m0 + m;
        int c = mg / 25, v = mg - c * 25;
        g_y[((size_t)(chbase + c) * T + n0 + tcol) * V + v] = rnd(Ys[m * 129 + tcol]);
    }
}

// ---------------------------------------------------------------------------
// FF + BN + residual + LeakyReLU. Block 64x256, warp 32x64, 3-stage. K=192.
// ---------------------------------------------------------------------------
__global__ __launch_bounds__(256) void k_ff(const float* __restrict__ x,
                                            const float* __restrict__ bias,
                                            const float* __restrict__ gamma,
                                            const float* __restrict__ beta,
                                            const float* __restrict__ mean,
                                            const float* __restrict__ var,
                                            float* __restrict__ out) {
    __shared__ __align__(16) float As[3][64 * 20];
    __shared__ __align__(16) float Bs[3][16 * 264];
    const int bz = blockIdx.z, m0 = blockIdx.y * 64, n0 = blockIdx.x * 256;
    const int tid = threadIdx.x, lane = tid & 31, wid = tid >> 5;
    const int g = lane >> 2, tg = lane & 3;
    const int wm = (wid >> 2) * 32, wn = (wid & 3) * 64;
    const float* Bg = g_y + (size_t)bz * C * TV + n0;
    const int am = tid >> 2, ak = (tid & 3) * 4;
    const int bk = tid >> 6, bn = (tid & 63) * 4;

    float acc[2][8][4] = {};

    auto load = [&](int buf, int kk) {
        cpa16(&As[buf][am * 20 + ak], g_wff + (m0 + am) * C + kk + ak);
#pragma unroll
        for (int r = 0; r < 16; r += 4)
            cpa16(&Bs[buf][(bk + r) * 264 + bn], Bg + (size_t)(kk + bk + r) * TV + bn);
    };
    auto compute = [&](int buf) {
#pragma unroll
        for (int ks = 0; ks < 2; ks++) {
            uint32_t a[2][4], b[8][2];
#pragma unroll
            for (int mi = 0; mi < 2; mi++) {
                const float* Ap = &As[buf][(wm + mi * 16) * 20 + ks * 8];
                a[mi][0] = LDU(Ap + g * 20 + tg);
                a[mi][1] = LDU(Ap + (g + 8) * 20 + tg);
                a[mi][2] = LDU(Ap + g * 20 + tg + 4);
                a[mi][3] = LDU(Ap + (g + 8) * 20 + tg + 4);
            }
#pragma unroll
            for (int ni = 0; ni < 8; ni++) {
                const float* Bp = &Bs[buf][ks * 8 * 264 + wn + ni * 8 + g];
                b[ni][0] = LDU(Bp + tg * 264);
                b[ni][1] = LDU(Bp + (tg + 4) * 264);
            }
#pragma unroll
            for (int mi = 0; mi < 2; mi++)
#pragma unroll
                for (int ni = 0; ni < 8; ni++) mma8(acc[mi][ni], a[mi], b[ni]);
        }
    };

    load(0, 0); cpcommit();
    load(1, 16); cpcommit();
    const int NIT = 12;
    for (int it = 0; it < NIT; ++it) {
        cpwait<1>();
        __syncthreads();
        int nx = it + 2;
        if (nx < NIT) load(nx - nx / 3 * 3, nx * 16);
        compute(it - it / 3 * 3);
        cpcommit();
    }
#pragma unroll
    for (int mi = 0; mi < 2; mi++) {
        int r0 = m0 + wm + mi * 16 + g;
        int r1 = r0 + 8;
        float sc0 = gamma[r0] * rsqrtf(var[r0] + 1e-5f);
        float sh0 = beta[r0] - mean[r0] * sc0;
        float bb0 = bias[r0];
        float sc1 = gamma[r1] * rsqrtf(var[r1] + 1e-5f);
        float sh1 = beta[r1] - mean[r1] * sc1;
        float bb1 = bias[r1];
#pragma unroll
        for (int ni = 0; ni < 8; ni++) {
            int col = n0 + wn + ni * 8 + 2 * tg;
            size_t i0 = (size_t)(bz * C + r0) * TV + col;
            size_t i1 = (size_t)(bz * C + r1) * TV + col;
            float2 x0 = *(const float2*)&x[i0];
            float2 x1 = *(const float2*)&x[i1];
            float z, o0x, o0y, o1x, o1y;
            z = x0.x + (acc[mi][ni][0] + bb0) * sc0 + sh0; o0x = z >= 0.f ? z : 0.1f * z;
            z = x0.y + (acc[mi][ni][1] + bb0) * sc0 + sh0; o0y = z >= 0.f ? z : 0.1f * z;
            z = x1.x + (acc[mi][ni][2] + bb1) * sc1 + sh1; o1x = z >= 0.f ? z : 0.1f * z;
            z = x1.y + (acc[mi][ni][3] + bb1) * sc1 + sh1; o1y = z >= 0.f ? z : 0.1f * z;
            *(float2*)&out[i0] = make_float2(o0x, o0y);
            *(float2*)&out[i1] = make_float2(o1x, o1y);
        }
    }
}

extern "C" void kernel_launch(void* const* d_in, const int* in_sizes, int n_in,
                              void* d_out, int out_size) {
    const float* x     = (const float*)d_in[0];
    const float* w_in  = (const float*)d_in[1];
    const float* b_in  = (const float*)d_in[2];
    const float* w_ff  = (const float*)d_in[3];
    const float* b_ff  = (const float*)d_in[4];
    const float* gamma = (const float*)d_in[5];
    const float* beta  = (const float*)d_in[6];
    const float* mean  = (const float*)d_in[7];
    const float* var   = (const float*)d_in[8];
    float* out = (float*)d_out;

    k_prep<<<432, 256>>>(w_in, w_ff);
    k_tr <<<NBATCH * C, 256>>>(x);
    k_qkv<<<dim3(25, 9, 32), 256>>>(b_in);
    k_att<<<dim3(2, 4, 96), 256>>>();
    k_av <<<dim3(2, 25, 96), 256>>>();
    k_ff <<<dim3(25, 3, 32), 256>>>(x, b_ff, gamma, beta, mean, var, out);
}

// round 6
// speedup vs baseline: 3.6038x; 1.0316x over previous
#include <cuda_runtime.h>
#include <cstdint>

#define NBATCH 32
#define C 192
#define C3 576
#define T 256
#define V 25
#define TV 6400
#define S 3
#define MID 64

// Scratch (device globals). All tensor-core operands stored pre-rounded to tf32.
__device__ float g_xT [NBATCH * C  * TV];   // [n][c][v][t] (tf32)
__device__ float g_qkv[NBATCH * C3 * TV];   // [n][d][v][t] (tf32)
__device__ float g_att[NBATCH * S * T * T]; // [n*s][q][t]  (tf32)
__device__ float g_y  [NBATCH * C  * TV];   // [n][ch][t][v] (tf32)
__device__ float g_win[C3 * C];             // tf32 weights
__device__ float g_wff[C * C];

__device__ __forceinline__ uint32_t f2tf(float f) {
    uint32_t r; asm("cvt.rna.tf32.f32 %0, %1;" : "=r"(r) : "f"(f)); return r;
}
__device__ __forceinline__ float rnd(float f) { return __uint_as_float(f2tf(f)); }
__device__ __forceinline__ void mma8(float* d, const uint32_t* a, const uint32_t* b) {
    asm volatile("mma.sync.aligned.m16n8k8.row.col.f32.tf32.tf32.f32 "
        "{%0,%1,%2,%3}, {%4,%5,%6,%7}, {%8,%9}, {%0,%1,%2,%3};"
        : "+f"(d[0]), "+f"(d[1]), "+f"(d[2]), "+f"(d[3])
        : "r"(a[0]), "r"(a[1]), "r"(a[2]), "r"(a[3]), "r"(b[0]), "r"(b[1]));
}
__device__ __forceinline__ void cpa16(void* s, const void* g) {
    uint32_t sa = (uint32_t)__cvta_generic_to_shared(s);
    asm volatile("cp.async.cg.shared.global [%0], [%1], 16;" :: "r"(sa), "l"(g));
}
__device__ __forceinline__ void cpcommit() { asm volatile("cp.async.commit_group;"); }
template <int N> __device__ __forceinline__ void cpwait() {
    asm volatile("cp.async.wait_group %0;" :: "n"(N));
}
__device__ __forceinline__ uint32_t LDU(const float* p) { return __float_as_uint(*p); }

// 3-way unrolled pipeline driver: load/compute always called with LITERAL buf.
#define PIPE3(NIT, BK, LOADF, COMPF)                                   \
    {                                                                  \
        LOADF(0, 0); cpcommit();                                       \
        LOADF(1, (BK)); cpcommit();                                    \
        int kk_ = 2 * (BK);                                            \
        int rem_ = (NIT);                                              \
        for (;;) {                                                     \
            cpwait<1>(); __syncthreads();                              \
            if (rem_ > 2) { LOADF(2, kk_); kk_ += (BK); }              \
            COMPF(0); cpcommit();                                      \
            if (--rem_ == 0) break;                                    \
            cpwait<1>(); __syncthreads();                              \
            if (rem_ > 2) { LOADF(0, kk_); kk_ += (BK); }              \
            COMPF(1); cpcommit();                                      \
            if (--rem_ == 0) break;                                    \
            cpwait<1>(); __syncthreads();                              \
            if (rem_ > 2) { LOADF(1, kk_); kk_ += (BK); }              \
            COMPF(2); cpcommit();                                      \
            if (--rem_ == 0) break;                                    \
        }                                                              \
    }

// ---------------------------------------------------------------------------
__global__ __launch_bounds__(256) void k_prep(const float* __restrict__ w_in,
                                              const float* __restrict__ w_ff) {
    int i = blockIdx.x * 256 + threadIdx.x;
    if (i < C3 * C) g_win[i] = rnd(w_in[i]);
    if (i < C * C)  g_wff[i] = rnd(w_ff[i]);
}

// x[n][c][t][v] -> xT[n][c][v][t] (tf32)
__global__ __launch_bounds__(256) void k_tr(const float* __restrict__ x) {
    __shared__ float sm[TV];
    size_t base = (size_t)blockIdx.x * TV;
    const int tid = threadIdx.x;
#pragma unroll
    for (int j = 0; j < 25; j++) sm[tid + j * 256] = x[base + tid + j * 256];
    __syncthreads();
#pragma unroll
    for (int j = 0; j < 25; j++) {
        int o = tid + j * 256;
        int t = o & 255, v = o >> 8;
        g_xT[base + o] = rnd(sm[t * 25 + v]);
    }
}

// ---------------------------------------------------------------------------
// QKV: block 64x256, warp 32x64, 3-stage pipeline. K=192, NIT=12.
// ---------------------------------------------------------------------------
__global__ __launch_bounds__(256) void k_qkv(const float* __restrict__ bias) {
    __shared__ __align__(16) float As[3][64 * 20];
    __shared__ __align__(16) float Bs[3][16 * 264];
    const int bz = blockIdx.z, m0 = blockIdx.y * 64, n0 = blockIdx.x * 256;
    const int tid = threadIdx.x, lane = tid & 31, wid = tid >> 5;
    const int g = lane >> 2, tg = lane & 3;
    const int wm = (wid >> 2) * 32, wn = (wid & 3) * 64;
    const float* Bg = g_xT + (size_t)bz * C * TV + n0;
    const int am = tid >> 2, ak = (tid & 3) * 4;
    const int bk = tid >> 6, bn = (tid & 63) * 4;

    float acc[2][8][4] = {};

#define QKV_LOAD(BUF, KK)                                                          \
    {                                                                              \
        cpa16(&As[BUF][am * 20 + ak], g_win + (m0 + am) * C + (KK) + ak);          \
        _Pragma("unroll")                                                          \
        for (int r = 0; r < 16; r += 4)                                            \
            cpa16(&Bs[BUF][(bk + r) * 264 + bn], Bg + (size_t)((KK) + bk + r) * TV + bn); \
    }
#define QKV_COMP(BUF)                                                              \
    {                                                                              \
        _Pragma("unroll")                                                          \
        for (int ks = 0; ks < 2; ks++) {                                           \
            uint32_t a[2][4], b[8][2];                                             \
            _Pragma("unroll")                                                      \
            for (int mi = 0; mi < 2; mi++) {                                       \
                const float* Ap = &As[BUF][(wm + mi * 16) * 20 + ks * 8];          \
                a[mi][0] = LDU(Ap + g * 20 + tg);                                  \
                a[mi][1] = LDU(Ap + (g + 8) * 20 + tg);                            \
                a[mi][2] = LDU(Ap + g * 20 + tg + 4);                              \
                a[mi][3] = LDU(Ap + (g + 8) * 20 + tg + 4);                        \
            }                                                                      \
            _Pragma("unroll")                                                      \
            for (int ni = 0; ni < 8; ni++) {                                       \
                const float* Bp = &Bs[BUF][ks * 8 * 264 + wn + ni * 8 + g];        \
                b[ni][0] = LDU(Bp + tg * 264);                                     \
                b[ni][1] = LDU(Bp + (tg + 4) * 264);                               \
            }                                                                      \
            _Pragma("unroll")                                                      \
            for (int mi = 0; mi < 2; mi++)                                         \
                _Pragma("unroll")                                                  \
                for (int ni = 0; ni < 8; ni++) mma8(acc[mi][ni], a[mi], b[ni]);    \
        }                                                                          \
    }

    PIPE3(12, 16, QKV_LOAD, QKV_COMP)

#pragma unroll
    for (int mi = 0; mi < 2; mi++) {
        int r0 = m0 + wm + mi * 16 + g;
        float b0 = bias[r0], b1 = bias[r0 + 8];
#pragma unroll
        for (int ni = 0; ni < 8; ni++) {
            int col = n0 + wn + ni * 8 + 2 * tg;
            float2 v0 = make_float2(rnd(acc[mi][ni][0] + b0), rnd(acc[mi][ni][1] + b0));
            float2 v1 = make_float2(rnd(acc[mi][ni][2] + b1), rnd(acc[mi][ni][3] + b1));
            *(float2*)&g_qkv[(size_t)(bz * C3 + r0) * TV + col] = v0;
            *(float2*)&g_qkv[(size_t)(bz * C3 + r0 + 8) * TV + col] = v1;
        }
    }
}

// ---------------------------------------------------------------------------
// Scores: att[ns][q][t] = tanh(sum_k K[k][q]*Q[k][t]/1600), K=1600, NIT=100.
// Block 64x128, warp 32x32.
// ---------------------------------------------------------------------------
__global__ __launch_bounds__(256) void k_att() {
    __shared__ __align__(16) float As[3][16 * 72];
    __shared__ __align__(16) float Bs[3][16 * 136];
    const int bz = blockIdx.z;
    const int nb = bz / 3, s = bz - nb * 3;
    const int m0 = blockIdx.y * 64, n0 = blockIdx.x * 128;
    const int tid = threadIdx.x, lane = tid & 31, wid = tid >> 5;
    const int g = lane >> 2, tg = lane & 3;
    const int wm = (wid >> 2) * 32, wn = (wid & 3) * 32;
    const float* Ag = g_qkv + ((size_t)nb * C3 + C + s * MID) * TV + m0;  // K [k][m]
    const float* Bg = g_qkv + ((size_t)nb * C3 + s * MID) * TV + n0;      // Q [k][n]
    const int ar = tid >> 4, ac = (tid & 15) * 4;
    const int br = tid >> 5, bc = (tid & 31) * 4;

    float acc[2][4][4] = {};

#define ATT_LOAD(BUF, KK)                                                          \
    {                                                                              \
        cpa16(&As[BUF][ar * 72 + ac], Ag + (size_t)((KK) + ar) * T + ac);          \
        cpa16(&Bs[BUF][br * 136 + bc], Bg + (size_t)((KK) + br) * T + bc);         \
        cpa16(&Bs[BUF][(br + 8) * 136 + bc], Bg + (size_t)((KK) + br + 8) * T + bc); \
    }
#define ATT_COMP(BUF)                                                              \
    {                                                                              \
        _Pragma("unroll")                                                          \
        for (int ks = 0; ks < 2; ks++) {                                           \
            uint32_t a[2][4], b[4][2];                                             \
            _Pragma("unroll")                                                      \
            for (int mi = 0; mi < 2; mi++) {                                       \
                const float* Ap = &As[BUF][ks * 8 * 72 + wm + mi * 16];            \
                a[mi][0] = LDU(Ap + tg * 72 + g);                                  \
                a[mi][1] = LDU(Ap + tg * 72 + g + 8);                              \
                a[mi][2] = LDU(Ap + (tg + 4) * 72 + g);                            \
                a[mi][3] = LDU(Ap + (tg + 4) * 72 + g + 8);                        \
            }                                                                      \
            _Pragma("unroll")                                                      \
            for (int ni = 0; ni < 4; ni++) {                                       \
                const float* Bp = &Bs[BUF][ks * 8 * 136 + wn + ni * 8 + g];        \
                b[ni][0] = LDU(Bp + tg * 136);                                     \
                b[ni][1] = LDU(Bp + (tg + 4) * 136);                               \
            }                                                                      \
            _Pragma("unroll")                                                      \
            for (int mi = 0; mi < 2; mi++)                                         \
                _Pragma("unroll")                                                  \
                for (int ni = 0; ni < 4; ni++) mma8(acc[mi][ni], a[mi], b[ni]);    \
        }                                                                          \
    }

    PIPE3(100, 16, ATT_LOAD, ATT_COMP)

    const float scl = 1.f / 1600.f;
#pragma unroll
    for (int mi = 0; mi < 2; mi++) {
        int q0r = m0 + wm + mi * 16 + g;
#pragma unroll
        for (int ni = 0; ni < 4; ni++) {
            int col = n0 + wn + ni * 8 + 2 * tg;
            float2 v0 = make_float2(rnd(tanhf(acc[mi][ni][0] * scl)), rnd(tanhf(acc[mi][ni][1] * scl)));
            float2 v1 = make_float2(rnd(tanhf(acc[mi][ni][2] * scl)), rnd(tanhf(acc[mi][ni][3] * scl)));
            *(float2*)&g_att[((size_t)bz * T + q0r) * T + col] = v0;
            *(float2*)&g_att[((size_t)bz * T + q0r + 8) * T + col] = v1;
        }
    }
}

// ---------------------------------------------------------------------------
// att.V: block 64x128, warp 32x32, K=256, NIT=16. Epilogue transpose via smem.
// ---------------------------------------------------------------------------
__global__ __launch_bounds__(256) void k_av() {
    __shared__ __align__(16) float SM[3 * 1280 + 3 * 2176];
    const int bz = blockIdx.z;
    const int nb = bz / 3, s = bz - nb * 3;
    const int m0 = blockIdx.y * 64, n0 = blockIdx.x * 128;
    const int tid = threadIdx.x, lane = tid & 31, wid = tid >> 5;
    const int g = lane >> 2, tg = lane & 3;
    const int wm = (wid >> 2) * 32, wn = (wid & 3) * 32;
    const float* Ag = g_qkv + ((size_t)nb * C3 + 2 * C + s * MID) * TV;  // V [m][k]
    const float* Bg = g_att + (size_t)bz * T * T + n0;
    const int am = tid >> 2, ak = (tid & 3) * 4;
    const int bk = tid >> 5, bn = (tid & 31) * 4;
    float* As0 = SM;
    float* Bs0 = SM + 3 * 1280;

    float acc[2][4][4] = {};

#define AV_LOAD(BUF, KK)                                                           \
    {                                                                              \
        cpa16(&As0[(BUF) * 1280 + am * 20 + ak], Ag + (size_t)(m0 + am) * T + (KK) + ak); \
        cpa16(&Bs0[(BUF) * 2176 + bk * 136 + bn], Bg + (size_t)((KK) + bk) * T + bn);     \
        cpa16(&Bs0[(BUF) * 2176 + (bk + 8) * 136 + bn], Bg + (size_t)((KK) + bk + 8) * T + bn); \
    }
#define AV_COMP(BUF)                                                               \
    {                                                                              \
        _Pragma("unroll")                                                          \
        for (int ks = 0; ks < 2; ks++) {                                           \
            uint32_t a[2][4], b[4][2];                                             \
            _Pragma("unroll")                                                      \
            for (int mi = 0; mi < 2; mi++) {                                       \
                const float* Ap = &As0[(BUF) * 1280 + (wm + mi * 16) * 20 + ks * 8]; \
                a[mi][0] = LDU(Ap + g * 20 + tg);                                  \
                a[mi][1] = LDU(Ap + (g + 8) * 20 + tg);                            \
                a[mi][2] = LDU(Ap + g * 20 + tg + 4);                              \
                a[mi][3] = LDU(Ap + (g + 8) * 20 + tg + 4);                        \
            }                                                                      \
            _Pragma("unroll")                                                      \
            for (int ni = 0; ni < 4; ni++) {                                       \
                const float* Bp = &Bs0[(BUF) * 2176 + ks * 8 * 136 + wn + ni * 8 + g]; \
                b[ni][0] = LDU(Bp + tg * 136);                                     \
                b[ni][1] = LDU(Bp + (tg + 4) * 136);                               \
            }                                                                      \
            _Pragma("unroll")                                                      \
            for (int mi = 0; mi < 2; mi++)                                         \
                _Pragma("unroll")                                                  \
                for (int ni = 0; ni < 4; ni++) mma8(acc[mi][ni], a[mi], b[ni]);    \
        }                                                                          \
    }

    PIPE3(16, 16, AV_LOAD, AV_COMP)

    __syncthreads();
    // stage 64x128 tile in smem (pitch 129), write y coalesced along v (tf32)
    float* Ys = SM;
#pragma unroll
    for (int mi = 0; mi < 2; mi++) {
        int r0 = wm + mi * 16 + g;
#pragma unroll
        for (int ni = 0; ni < 4; ni++) {
            int col = wn + ni * 8 + 2 * tg;
            Ys[r0 * 129 + col]           = acc[mi][ni][0];
            Ys[r0 * 129 + col + 1]       = acc[mi][ni][1];
            Ys[(r0 + 8) * 129 + col]     = acc[mi][ni][2];
            Ys[(r0 + 8) * 129 + col + 1] = acc[mi][ni][3];
        }
    }
    __syncthreads();
    const int chbase = nb * C + s * MID;
#pragma unroll
    for (int it = 0; it < 32; ++it) {
        int e = tid + it * 256;
        int m = e & 63, tcol = e >> 6;
        int mg = m0 + m;
        int c = mg / 25, v = mg - c * 25;
        g_y[((size_t)(chbase + c) * T + n0 + tcol) * V + v] = rnd(Ys[m * 129 + tcol]);
    }
}

// ---------------------------------------------------------------------------
// FF + BN + residual + LeakyReLU. Block 64x256, warp 32x64. K=192, NIT=12.
// ---------------------------------------------------------------------------
__global__ __launch_bounds__(256) void k_ff(const float* __restrict__ x,
                                            const float* __restrict__ bias,
                                            const float* __restrict__ gamma,
                                            const float* __restrict__ beta,
                                            const float* __restrict__ mean,
                                            const float* __restrict__ var,
                                            float* __restrict__ out) {
    __shared__ __align__(16) float As[3][64 * 20];
    __shared__ __align__(16) float Bs[3][16 * 264];
    const int bz = blockIdx.z, m0 = blockIdx.y * 64, n0 = blockIdx.x * 256;
    const int tid = threadIdx.x, lane = tid & 31, wid = tid >> 5;
    const int g = lane >> 2, tg = lane & 3;
    const int wm = (wid >> 2) * 32, wn = (wid & 3) * 64;
    const float* Bg = g_y + (size_t)bz * C * TV + n0;
    const int am = tid >> 2, ak = (tid & 3) * 4;
    const int bk = tid >> 6, bn = (tid & 63) * 4;

    float acc[2][8][4] = {};

#define FF_LOAD(BUF, KK)                                                           \
    {                                                                              \
        cpa16(&As[BUF][am * 20 + ak], g_wff + (m0 + am) * C + (KK) + ak);          \
        _Pragma("unroll")                                                          \
        for (int r = 0; r < 16; r += 4)                                            \
            cpa16(&Bs[BUF][(bk + r) * 264 + bn], Bg + (size_t)((KK) + bk + r) * TV + bn); \
    }

    PIPE3(12, 16, FF_LOAD, QKV_COMP)

#pragma unroll
    for (int mi = 0; mi < 2; mi++) {
        int r0 = m0 + wm + mi * 16 + g;
        int r1 = r0 + 8;
        float sc0 = gamma[r0] * rsqrtf(var[r0] + 1e-5f);
        float sh0 = beta[r0] - mean[r0] * sc0;
        float bb0 = bias[r0];
        float sc1 = gamma[r1] * rsqrtf(var[r1] + 1e-5f);
        float sh1 = beta[r1] - mean[r1] * sc1;
        float bb1 = bias[r1];
#pragma unroll
        for (int ni = 0; ni < 8; ni++) {
            int col = n0 + wn + ni * 8 + 2 * tg;
            size_t i0 = (size_t)(bz * C + r0) * TV + col;
            size_t i1 = (size_t)(bz * C + r1) * TV + col;
            float2 x0 = *(const float2*)&x[i0];
            float2 x1 = *(const float2*)&x[i1];
            float z, o0x, o0y, o1x, o1y;
            z = x0.x + (acc[mi][ni][0] + bb0) * sc0 + sh0; o0x = z >= 0.f ? z : 0.1f * z;
            z = x0.y + (acc[mi][ni][1] + bb0) * sc0 + sh0; o0y = z >= 0.f ? z : 0.1f * z;
            z = x1.x + (acc[mi][ni][2] + bb1) * sc1 + sh1; o1x = z >= 0.f ? z : 0.1f * z;
            z = x1.y + (acc[mi][ni][3] + bb1) * sc1 + sh1; o1y = z >= 0.f ? z : 0.1f * z;
            *(float2*)&out[i0] = make_float2(o0x, o0y);
            *(float2*)&out[i1] = make_float2(o1x, o1y);
        }
    }
}

extern "C" void kernel_launch(void* const* d_in, const int* in_sizes, int n_in,
                              void* d_out, int out_size) {
    const float* x     = (const float*)d_in[0];
    const float* w_in  = (const float*)d_in[1];
    const float* b_in  = (const float*)d_in[2];
    const float* w_ff  = (const float*)d_in[3];
    const float* b_ff  = (const float*)d_in[4];
    const float* gamma = (const float*)d_in[5];
    const float* beta  = (const float*)d_in[6];
    const float* mean  = (const float*)d_in[7];
    const float* var   = (const float*)d_in[8];
    float* out = (float*)d_out;

    k_prep<<<432, 256>>>(w_in, w_ff);
    k_tr <<<NBATCH * C, 256>>>(x);
    k_qkv<<<dim3(25, 9, 32), 256>>>(b_in);
    k_att<<<dim3(2, 4, 96), 256>>>();
    k_av <<<dim3(2, 25, 96), 256>>>();
    k_ff <<<dim3(25, 3, 32), 256>>>(x, b_ff, gamma, beta, mean, var, out);
}